// round 5
// baseline (speedup 1.0000x reference)
#include <cuda_runtime.h>

#define M_PILLARS 16384
#define N_POINTS  4096
#define C_FEAT    64
#define RADIUS2   1.0f
#define VX        0.16f
#define VY        0.16f
#define PCY      -25.6f

#define GW        52            // grid cells per dim (cell size = 1.0 = R)
#define NCELLS    (GW * GW)     // 2704
#define SENT      0x7fffffffu

__device__ int    g_bin_start[NCELLS + 1];
__device__ float4 g_sorted[N_POINTS];    // x, y, idx(bits), pad

__device__ __forceinline__ int cell_of(float x, float y) {
    int gx = (int)floorf(x);            // cell size 1.0, x in [0, 51.2)
    int gy = (int)floorf(y + 25.6f);    // y in [-25.6, 25.6)
    gx = min(max(gx, 0), GW - 1);
    gy = min(max(gy, 0), GW - 1);
    return gy * GW + gx;
}

// ── Single-block prep: count + 3-level scan + scatter ───────────────────
__global__ __launch_bounds__(1024)
void k_prep(const float* __restrict__ seg_points) {
    __shared__ int cnt[NCELLS];
    __shared__ int cur[NCELLS];
    __shared__ int wsum[32];

    const int t    = threadIdx.x;
    const int lane = t & 31;
    const int w    = t >> 5;

    // zero counts
    for (int i = t; i < NCELLS; i += 1024) cnt[i] = 0;
    __syncthreads();

    // count (keep point data in registers for scatter)
    float xk[4], yk[4];
    int   ck[4];
    #pragma unroll
    for (int k = 0; k < 4; k++) {
        const int i = t + k * 1024;
        float x = seg_points[i * 3 + 0];
        float y = seg_points[i * 3 + 1];
        xk[k] = x; yk[k] = y;
        ck[k] = cell_of(x, y);
        atomicAdd(&cnt[ck[k]], 1);
    }
    __syncthreads();

    // 3-level exclusive scan: 3 cells per thread
    const int base = t * 3;
    int v0 = (base + 0 < NCELLS) ? cnt[base + 0] : 0;
    int v1 = (base + 1 < NCELLS) ? cnt[base + 1] : 0;
    int v2 = (base + 2 < NCELLS) ? cnt[base + 2] : 0;
    int s  = v0 + v1 + v2;

    // warp inclusive scan of s
    int incl = s;
    #pragma unroll
    for (int d = 1; d < 32; d <<= 1) {
        int up = __shfl_up_sync(0xffffffffu, incl, d);
        if (lane >= d) incl += up;
    }
    if (lane == 31) wsum[w] = incl;
    __syncthreads();
    if (w == 0) {
        int ws = wsum[lane];
        int wi = ws;
        #pragma unroll
        for (int d = 1; d < 32; d <<= 1) {
            int up = __shfl_up_sync(0xffffffffu, wi, d);
            if (lane >= d) wi += up;
        }
        wsum[lane] = wi - ws;   // exclusive warp offsets
    }
    __syncthreads();

    const int excl = incl - s + wsum[w];   // exclusive prefix for this chunk
    if (base + 0 < NCELLS) { g_bin_start[base + 0] = excl;          cur[base + 0] = excl; }
    if (base + 1 < NCELLS) { g_bin_start[base + 1] = excl + v0;     cur[base + 1] = excl + v0; }
    if (base + 2 < NCELLS) { g_bin_start[base + 2] = excl + v0 + v1; cur[base + 2] = excl + v0 + v1; }
    if (t == 0) g_bin_start[NCELLS] = N_POINTS;   // all points bin (clamped)
    __syncthreads();

    // scatter
    #pragma unroll
    for (int k = 0; k < 4; k++) {
        const int pos = atomicAdd(&cur[ck[k]], 1);
        g_sorted[pos] = make_float4(xk[k], yk[k], __int_as_float(t + k * 1024), 0.0f);
    }
}

// ── Query (thread-per-pillar) + fuse (warp-per-pillar) ──────────────────
__global__ __launch_bounds__(256)
void k_query_fuse(const float* __restrict__ pillar_feature,
                  const int*   __restrict__ coors,
                  const float* __restrict__ seg_feats,
                  float*       __restrict__ out) {
    __shared__ int4 sidx[256];

    const int t = threadIdx.x;
    const int m = blockIdx.x * 256 + t;

    // ── Phase A: per-thread ball query (4 smallest in-radius indices) ──
    {
        const float px = ((float)__ldg(&coors[m * 4 + 3]) + 0.5f) * VX;
        const float py = ((float)__ldg(&coors[m * 4 + 2]) + 0.5f) * VY + PCY;

        const int cx = min(max((int)floorf(px), 0), GW - 1);
        const int cy = min(max((int)floorf(py + 25.6f), 0), GW - 1);
        const int cx0 = max(cx - 1, 0), cx1 = min(cx + 1, GW - 1);
        const int cy0 = max(cy - 1, 0), cy1 = min(cy + 1, GW - 1);

        unsigned c0 = SENT, c1 = SENT, c2 = SENT, c3 = SENT;

        for (int gy = cy0; gy <= cy1; gy++) {
            const int s = g_bin_start[gy * GW + cx0];
            const int e = g_bin_start[gy * GW + cx1 + 1];
            for (int j = s; j < e; j++) {
                float4 p = g_sorted[j];
                float dx = px - p.x;
                float dy = py - p.y;
                if (dx * dx + dy * dy < RADIUS2) {
                    unsigned v = (unsigned)__float_as_int(p.z);
                    if (v < c3) {
                        c3 = v;
                        unsigned tmp;
                        if (c3 < c2) { tmp = c2; c2 = c3; c3 = tmp; }
                        if (c2 < c1) { tmp = c1; c1 = c2; c2 = tmp; }
                        if (c1 < c0) { tmp = c0; c0 = c1; c1 = tmp; }
                    }
                }
            }
        }

        int i0, i1, i2, i3;
        if (c0 == SENT) { i0 = i1 = i2 = i3 = 0; }
        else {
            i0 = (int)c0;
            i1 = (c1 == SENT) ? i0 : (int)c1;
            i2 = (c2 == SENT) ? i0 : (int)c2;
            i3 = (c3 == SENT) ? i0 : (int)c3;
        }
        sidx[t] = make_int4(i0, i1, i2, i3);
    }
    __syncthreads();

    // ── Phase B: warp-per-pillar coalesced fuse (2 channels per lane) ──
    const int warp = t >> 5;
    const int lane = t & 31;
    const int pbase = blockIdx.x * 256 + warp * 32;

    #pragma unroll 4
    for (int k = 0; k < 32; k++) {
        const int p = pbase + k;
        const int4 id = sidx[warp * 32 + k];

        const size_t mrow = (size_t)p * C_FEAT;
        float v0 = pillar_feature[mrow + lane];
        float v1 = pillar_feature[mrow + lane + 32];

        // Reference quirk: flag = (sum of indices) > 0
        if (id.x + id.y + id.z + id.w > 0) {
            const size_t r0 = (size_t)id.x * C_FEAT;
            const size_t r1 = (size_t)id.y * C_FEAT;
            const size_t r2 = (size_t)id.z * C_FEAT;
            const size_t r3 = (size_t)id.w * C_FEAT;

            float a0 = seg_feats[r0 + lane];
            float a1 = seg_feats[r1 + lane];
            float a2 = seg_feats[r2 + lane];
            float a3 = seg_feats[r3 + lane];
            float b0 = seg_feats[r0 + lane + 32];
            float b1 = seg_feats[r1 + lane + 32];
            float b2 = seg_feats[r2 + lane + 32];
            float b3 = seg_feats[r3 + lane + 32];

            v0 += fmaxf(fmaxf(a0, a1), fmaxf(a2, a3));
            v1 += fmaxf(fmaxf(b0, b1), fmaxf(b2, b3));
        }

        out[mrow + lane]      = v0;
        out[mrow + lane + 32] = v1;
    }
}

extern "C" void kernel_launch(void* const* d_in, const int* in_sizes, int n_in,
                              void* d_out, int out_size) {
    const float* pillar_feature = (const float*)d_in[0];  // [M, 64]
    const int*   coors          = (const int*)  d_in[1];  // [M, 4]
    const float* seg_feats      = (const float*)d_in[2];  // [N, 64]
    const float* seg_points     = (const float*)d_in[3];  // [N, 3]
    float* out = (float*)d_out;                            // [M, 64]

    k_prep<<<1, 1024>>>(seg_points);
    k_query_fuse<<<M_PILLARS / 256, 256>>>(pillar_feature, coors, seg_feats, out);
}

// round 7
// speedup vs baseline: 1.5085x; 1.5085x over previous
#include <cuda_runtime.h>

#define M_PILLARS 16384
#define N_POINTS  4096
#define C_FEAT    64
#define RADIUS2   1.0f
#define VX        0.16f
#define VY        0.16f
#define PCY      -25.6f

#define GW        52            // grid cells per dim (cell size = 1.0 = R)
#define NCELLS    (GW * GW)     // 2704
#define SENT      0x7fffffffu

__device__ int    g_bin_start[NCELLS + 1];
__device__ float4 g_sorted[N_POINTS];    // x, y, idx(bits), pad

__device__ __forceinline__ int cell_of(float x, float y) {
    int gx = (int)floorf(x);            // cell size 1.0, x in [0, 51.2)
    int gy = (int)floorf(y + 25.6f);    // y in [-25.6, 25.6)
    gx = min(max(gx, 0), GW - 1);
    gy = min(max(gy, 0), GW - 1);
    return gy * GW + gx;
}

// ── Single-block prep: count + 3-level scan + scatter ───────────────────
__global__ __launch_bounds__(1024)
void k_prep(const float* __restrict__ seg_points) {
    __shared__ int cnt[NCELLS];
    __shared__ int cur[NCELLS];
    __shared__ int wsum[32];

    const int t    = threadIdx.x;
    const int lane = t & 31;
    const int w    = t >> 5;

    for (int i = t; i < NCELLS; i += 1024) cnt[i] = 0;
    __syncthreads();

    float xk[4], yk[4];
    int   ck[4];
    #pragma unroll
    for (int k = 0; k < 4; k++) {
        const int i = t + k * 1024;
        float x = seg_points[i * 3 + 0];
        float y = seg_points[i * 3 + 1];
        xk[k] = x; yk[k] = y;
        ck[k] = cell_of(x, y);
        atomicAdd(&cnt[ck[k]], 1);
    }
    __syncthreads();

    // 3-level exclusive scan: 3 cells per thread
    const int base = t * 3;
    int v0 = (base + 0 < NCELLS) ? cnt[base + 0] : 0;
    int v1 = (base + 1 < NCELLS) ? cnt[base + 1] : 0;
    int v2 = (base + 2 < NCELLS) ? cnt[base + 2] : 0;
    int s  = v0 + v1 + v2;

    int incl = s;
    #pragma unroll
    for (int d = 1; d < 32; d <<= 1) {
        int up = __shfl_up_sync(0xffffffffu, incl, d);
        if (lane >= d) incl += up;
    }
    if (lane == 31) wsum[w] = incl;
    __syncthreads();
    if (w == 0) {
        int ws = wsum[lane];
        int wi = ws;
        #pragma unroll
        for (int d = 1; d < 32; d <<= 1) {
            int up = __shfl_up_sync(0xffffffffu, wi, d);
            if (lane >= d) wi += up;
        }
        wsum[lane] = wi - ws;
    }
    __syncthreads();

    const int excl = incl - s + wsum[w];
    if (base + 0 < NCELLS) { g_bin_start[base + 0] = excl;           cur[base + 0] = excl; }
    if (base + 1 < NCELLS) { g_bin_start[base + 1] = excl + v0;      cur[base + 1] = excl + v0; }
    if (base + 2 < NCELLS) { g_bin_start[base + 2] = excl + v0 + v1; cur[base + 2] = excl + v0 + v1; }
    if (t == 0) g_bin_start[NCELLS] = N_POINTS;
    __syncthreads();

    #pragma unroll
    for (int k = 0; k < 4; k++) {
        const int pos = atomicAdd(&cur[ck[k]], 1);
        g_sorted[pos] = make_float4(xk[k], yk[k], __int_as_float(t + k * 1024), 0.0f);
    }
}

// ── Query (4 lanes per pillar) + fuse (warp per 8 pillars) ──────────────
// 256 threads/block → 64 pillars/block → grid 256
__global__ __launch_bounds__(256)
void k_query_fuse(const float* __restrict__ pillar_feature,
                  const int*   __restrict__ coors,
                  const float* __restrict__ seg_feats,
                  float*       __restrict__ out) {
    __shared__ int4 sidx[64];

    const int t    = threadIdx.x;
    const int warp = t >> 5;
    const int lane = t & 31;
    const int sub  = lane & 3;            // lane within quad
    const int pl   = t >> 2;              // pillar within block (0..63)
    const int m    = blockIdx.x * 64 + pl;

    // ── Phase A: quad ball query ──
    {
        const float px = ((float)__ldg(&coors[m * 4 + 3]) + 0.5f) * VX;
        const float py = ((float)__ldg(&coors[m * 4 + 2]) + 0.5f) * VY + PCY;

        const int cx = min(max((int)floorf(px), 0), GW - 1);
        const int cy = min(max((int)floorf(py + 25.6f), 0), GW - 1);
        const int cx0 = max(cx - 1, 0), cx1 = min(cx + 1, GW - 1);
        const int cy0 = max(cy - 1, 0), cy1 = min(cy + 1, GW - 1);

        // per-lane 4 smallest in-radius indices (sorted ascending)
        unsigned c0 = SENT, c1 = SENT, c2 = SENT, c3 = SENT;

        for (int gy = cy0; gy <= cy1; gy++) {
            const int s = g_bin_start[gy * GW + cx0];
            const int e = g_bin_start[gy * GW + cx1 + 1];
            for (int j = s + sub; j < e; j += 4) {
                float4 p = g_sorted[j];
                float dx = px - p.x;
                float dy = py - p.y;
                if (dx * dx + dy * dy < RADIUS2) {
                    unsigned v = (unsigned)__float_as_int(p.z);
                    if (v < c3) {
                        c3 = v;
                        unsigned tmp;
                        if (c3 < c2) { tmp = c2; c2 = c3; c3 = tmp; }
                        if (c2 < c1) { tmp = c1; c1 = c2; c2 = tmp; }
                        if (c1 < c0) { tmp = c0; c0 = c1; c1 = tmp; }
                    }
                }
            }
        }

        // quad merge: ALWAYS 4 rounds, no divergent exit around shuffles.
        unsigned res0, res1, res2, res3;
        {
            unsigned a, mn;
            #define QMIN(dst)                                            \
                a  = min(c0, __shfl_xor_sync(0xffffffffu, c0, 1, 4));    \
                mn = min(a,  __shfl_xor_sync(0xffffffffu, a,  2, 4));    \
                dst = mn;                                                \
                if (c0 == mn && mn != SENT) { c0 = c1; c1 = c2; c2 = c3; c3 = SENT; }
            QMIN(res0)
            QMIN(res1)
            QMIN(res2)
            QMIN(res3)
            #undef QMIN
        }

        int i0, i1, i2, i3;
        if (res0 == SENT) { i0 = i1 = i2 = i3 = 0; }
        else {
            i0 = (int)res0;
            i1 = (res1 == SENT) ? i0 : (int)res1;
            i2 = (res2 == SENT) ? i0 : (int)res2;
            i3 = (res3 == SENT) ? i0 : (int)res3;
        }
        if (sub == 0) sidx[pl] = make_int4(i0, i1, i2, i3);
    }
    __syncthreads();

    // ── Phase B: warp-per-pillar coalesced fuse (8 pillars per warp) ──
    const int pbase = blockIdx.x * 64 + warp * 8;

    #pragma unroll
    for (int k = 0; k < 8; k++) {
        const int p = pbase + k;
        const int4 id = sidx[warp * 8 + k];

        const size_t mrow = (size_t)p * C_FEAT;
        float v0 = pillar_feature[mrow + lane];
        float v1 = pillar_feature[mrow + lane + 32];

        // Reference quirk: flag = (sum of indices) > 0
        if (id.x + id.y + id.z + id.w > 0) {
            const size_t r0 = (size_t)id.x * C_FEAT;
            const size_t r1 = (size_t)id.y * C_FEAT;
            const size_t r2 = (size_t)id.z * C_FEAT;
            const size_t r3 = (size_t)id.w * C_FEAT;

            float a0 = seg_feats[r0 + lane];
            float a1 = seg_feats[r1 + lane];
            float a2 = seg_feats[r2 + lane];
            float a3 = seg_feats[r3 + lane];
            float b0 = seg_feats[r0 + lane + 32];
            float b1 = seg_feats[r1 + lane + 32];
            float b2 = seg_feats[r2 + lane + 32];
            float b3 = seg_feats[r3 + lane + 32];

            v0 += fmaxf(fmaxf(a0, a1), fmaxf(a2, a3));
            v1 += fmaxf(fmaxf(b0, b1), fmaxf(b2, b3));
        }

        out[mrow + lane]      = v0;
        out[mrow + lane + 32] = v1;
    }
}

extern "C" void kernel_launch(void* const* d_in, const int* in_sizes, int n_in,
                              void* d_out, int out_size) {
    const float* pillar_feature = (const float*)d_in[0];  // [M, 64]
    const int*   coors          = (const int*)  d_in[1];  // [M, 4]
    const float* seg_feats      = (const float*)d_in[2];  // [N, 64]
    const float* seg_points     = (const float*)d_in[3];  // [N, 3]
    float* out = (float*)d_out;                            // [M, 64]

    k_prep<<<1, 1024>>>(seg_points);
    k_query_fuse<<<M_PILLARS / 64, 256>>>(pillar_feature, coors, seg_feats, out);
}

// round 8
// speedup vs baseline: 1.6879x; 1.1189x over previous
#include <cuda_runtime.h>

#define M_PILLARS 16384
#define N_POINTS  4096
#define C_FEAT    64
#define RADIUS2   1.0f
#define VX        0.16f
#define VY        0.16f
#define PCY      -25.6f

#define GW        52            // grid cells per dim (cell size = 1.0 = R)
#define NCELLS    (GW * GW)     // 2704
#define SENT      0x7fffffffu

__device__ int    g_bin_start[NCELLS + 1];
__device__ float4 g_sorted[N_POINTS];    // x, y, idx(bits), pad

__device__ __forceinline__ int cell_of(float x, float y) {
    int gx = (int)floorf(x);            // cell size 1.0, x in [0, 51.2)
    int gy = (int)floorf(y + 25.6f);    // y in [-25.6, 25.6)
    gx = min(max(gx, 0), GW - 1);
    gy = min(max(gy, 0), GW - 1);
    return gy * GW + gx;
}

// ── Single-block prep: count + 3-level scan + scatter ───────────────────
__global__ __launch_bounds__(1024)
void k_prep(const float* __restrict__ seg_points) {
    __shared__ int cnt[NCELLS];
    __shared__ int cur[NCELLS];
    __shared__ int wsum[32];

    const int t    = threadIdx.x;
    const int lane = t & 31;
    const int w    = t >> 5;

    for (int i = t; i < NCELLS; i += 1024) cnt[i] = 0;
    __syncthreads();

    float xk[4], yk[4];
    int   ck[4];
    #pragma unroll
    for (int k = 0; k < 4; k++) {
        const int i = t + k * 1024;
        float x = seg_points[i * 3 + 0];
        float y = seg_points[i * 3 + 1];
        xk[k] = x; yk[k] = y;
        ck[k] = cell_of(x, y);
        atomicAdd(&cnt[ck[k]], 1);
    }
    __syncthreads();

    // 3-level exclusive scan: 3 cells per thread
    const int base = t * 3;
    int v0 = (base + 0 < NCELLS) ? cnt[base + 0] : 0;
    int v1 = (base + 1 < NCELLS) ? cnt[base + 1] : 0;
    int v2 = (base + 2 < NCELLS) ? cnt[base + 2] : 0;
    int s  = v0 + v1 + v2;

    int incl = s;
    #pragma unroll
    for (int d = 1; d < 32; d <<= 1) {
        int up = __shfl_up_sync(0xffffffffu, incl, d);
        if (lane >= d) incl += up;
    }
    if (lane == 31) wsum[w] = incl;
    __syncthreads();
    if (w == 0) {
        int ws = wsum[lane];
        int wi = ws;
        #pragma unroll
        for (int d = 1; d < 32; d <<= 1) {
            int up = __shfl_up_sync(0xffffffffu, wi, d);
            if (lane >= d) wi += up;
        }
        wsum[lane] = wi - ws;
    }
    __syncthreads();

    const int excl = incl - s + wsum[w];
    if (base + 0 < NCELLS) { g_bin_start[base + 0] = excl;           cur[base + 0] = excl; }
    if (base + 1 < NCELLS) { g_bin_start[base + 1] = excl + v0;      cur[base + 1] = excl + v0; }
    if (base + 2 < NCELLS) { g_bin_start[base + 2] = excl + v0 + v1; cur[base + 2] = excl + v0 + v1; }
    if (t == 0) g_bin_start[NCELLS] = N_POINTS;
    __syncthreads();

    #pragma unroll
    for (int k = 0; k < 4; k++) {
        const int pos = atomicAdd(&cur[ck[k]], 1);
        g_sorted[pos] = make_float4(xk[k], yk[k], __int_as_float(t + k * 1024), 0.0f);
    }
}

// ── Query (8 lanes per pillar) + fuse (warp per 4 pillars) ──────────────
// 256 threads/block → 32 pillars/block → grid 512
__global__ __launch_bounds__(256)
void k_query_fuse(const float* __restrict__ pillar_feature,
                  const int*   __restrict__ coors,
                  const float* __restrict__ seg_feats,
                  float*       __restrict__ out) {
    __shared__ int4 sidx[32];

    const int t    = threadIdx.x;
    const int warp = t >> 5;
    const int lane = t & 31;
    const int sub  = lane & 7;            // lane within octet
    const int pl   = t >> 3;              // pillar within block (0..31)
    const int m    = blockIdx.x * 32 + pl;

    // ── Phase A: octet ball query ──
    {
        const float px = ((float)__ldg(&coors[m * 4 + 3]) + 0.5f) * VX;
        const float py = ((float)__ldg(&coors[m * 4 + 2]) + 0.5f) * VY + PCY;

        const int cx = min(max((int)floorf(px), 0), GW - 1);
        const int cy = min(max((int)floorf(py + 25.6f), 0), GW - 1);
        const int cx0 = max(cx - 1, 0), cx1 = min(cx + 1, GW - 1);
        const int cy0 = max(cy - 1, 0), cy1 = min(cy + 1, GW - 1);
        const int cyn = cy1 - cy0;        // 1 or 2 extra rows

        // Hoist all row ranges: 6 independent loads (MLP)
        int s0, e0, s1, e1, s2, e2;
        s0 = __ldg(&g_bin_start[cy0 * GW + cx0]);
        e0 = __ldg(&g_bin_start[cy0 * GW + cx1 + 1]);
        {
            const int gy1 = min(cy0 + 1, cy1);
            s1 = __ldg(&g_bin_start[gy1 * GW + cx0]);
            e1 = __ldg(&g_bin_start[gy1 * GW + cx1 + 1]);
            const int gy2 = cy1;
            s2 = __ldg(&g_bin_start[gy2 * GW + cx0]);
            e2 = __ldg(&g_bin_start[gy2 * GW + cx1 + 1]);
        }
        if (cyn < 1) { s1 = 0; e1 = 0; }
        if (cyn < 2) { s2 = 0; e2 = 0; }

        // per-lane 4 smallest in-radius indices (sorted ascending)
        unsigned c0 = SENT, c1 = SENT, c2 = SENT, c3 = SENT;

        #define SCAN_ROW(S, E)                                               \
            for (int j = (S) + sub; j < (E); j += 8) {                       \
                float4 p = g_sorted[j];                                      \
                float dx = px - p.x;                                         \
                float dy = py - p.y;                                         \
                if (dx * dx + dy * dy < RADIUS2) {                           \
                    unsigned v = (unsigned)__float_as_int(p.z);              \
                    if (v < c3) {                                            \
                        c3 = v;                                              \
                        unsigned tmp;                                        \
                        if (c3 < c2) { tmp = c2; c2 = c3; c3 = tmp; }        \
                        if (c2 < c1) { tmp = c1; c1 = c2; c2 = tmp; }        \
                        if (c1 < c0) { tmp = c0; c0 = c1; c1 = tmp; }        \
                    }                                                        \
                }                                                            \
            }
        SCAN_ROW(s0, e0)
        SCAN_ROW(s1, e1)
        SCAN_ROW(s2, e2)
        #undef SCAN_ROW

        // octet merge: ALWAYS 4 rounds, no divergent exit around shuffles.
        unsigned res0, res1, res2, res3;
        {
            unsigned a, mn;
            #define QMIN(dst)                                                \
                a  = min(c0, __shfl_xor_sync(0xffffffffu, c0, 1, 8));        \
                a  = min(a,  __shfl_xor_sync(0xffffffffu, a,  2, 8));        \
                mn = min(a,  __shfl_xor_sync(0xffffffffu, a,  4, 8));        \
                dst = mn;                                                    \
                if (c0 == mn && mn != SENT) { c0 = c1; c1 = c2; c2 = c3; c3 = SENT; }
            QMIN(res0)
            QMIN(res1)
            QMIN(res2)
            QMIN(res3)
            #undef QMIN
        }

        int i0, i1, i2, i3;
        if (res0 == SENT) { i0 = i1 = i2 = i3 = 0; }
        else {
            i0 = (int)res0;
            i1 = (res1 == SENT) ? i0 : (int)res1;
            i2 = (res2 == SENT) ? i0 : (int)res2;
            i3 = (res3 == SENT) ? i0 : (int)res3;
        }
        if (sub == 0) sidx[pl] = make_int4(i0, i1, i2, i3);
    }
    __syncthreads();

    // ── Phase B: warp-per-pillar coalesced fuse (4 pillars per warp) ──
    const int pbase = blockIdx.x * 32 + warp * 4;

    #pragma unroll
    for (int k = 0; k < 4; k++) {
        const int p = pbase + k;
        const int4 id = sidx[warp * 4 + k];

        const size_t mrow = (size_t)p * C_FEAT;
        float v0 = pillar_feature[mrow + lane];
        float v1 = pillar_feature[mrow + lane + 32];

        // Reference quirk: flag = (sum of indices) > 0
        if (id.x + id.y + id.z + id.w > 0) {
            const size_t r0 = (size_t)id.x * C_FEAT;
            const size_t r1 = (size_t)id.y * C_FEAT;
            const size_t r2 = (size_t)id.z * C_FEAT;
            const size_t r3 = (size_t)id.w * C_FEAT;

            float a0 = seg_feats[r0 + lane];
            float a1 = seg_feats[r1 + lane];
            float a2 = seg_feats[r2 + lane];
            float a3 = seg_feats[r3 + lane];
            float b0 = seg_feats[r0 + lane + 32];
            float b1 = seg_feats[r1 + lane + 32];
            float b2 = seg_feats[r2 + lane + 32];
            float b3 = seg_feats[r3 + lane + 32];

            v0 += fmaxf(fmaxf(a0, a1), fmaxf(a2, a3));
            v1 += fmaxf(fmaxf(b0, b1), fmaxf(b2, b3));
        }

        out[mrow + lane]      = v0;
        out[mrow + lane + 32] = v1;
    }
}

extern "C" void kernel_launch(void* const* d_in, const int* in_sizes, int n_in,
                              void* d_out, int out_size) {
    const float* pillar_feature = (const float*)d_in[0];  // [M, 64]
    const int*   coors          = (const int*)  d_in[1];  // [M, 4]
    const float* seg_feats      = (const float*)d_in[2];  // [N, 64]
    const float* seg_points     = (const float*)d_in[3];  // [N, 3]
    float* out = (float*)d_out;                            // [M, 64]

    k_prep<<<1, 1024>>>(seg_points);
    k_query_fuse<<<M_PILLARS / 32, 256>>>(pillar_feature, coors, seg_feats, out);
}

// round 9
// speedup vs baseline: 1.7171x; 1.0173x over previous
#include <cuda_runtime.h>

#define M_PILLARS 16384
#define N_POINTS  4096
#define C_FEAT    64
#define RADIUS2   1.0f
#define VX        0.16f
#define VY        0.16f
#define PCY      -25.6f

#define GW        52            // grid cells per dim (cell size = 1.0 = R)
#define NCELLS    (GW * GW)     // 2704
#define SENT      0x7fffffffu

__device__ int    g_bin_start[NCELLS + 1];
__device__ float4 g_sorted[N_POINTS];    // x, y, idx(bits), pad

__device__ __forceinline__ int cell_of(float x, float y) {
    int gx = (int)floorf(x);            // cell size 1.0, x in [0, 51.2)
    int gy = (int)floorf(y + 25.6f);    // y in [-25.6, 25.6)
    gx = min(max(gx, 0), GW - 1);
    gy = min(max(gy, 0), GW - 1);
    return gy * GW + gx;
}

// ── Single-block prep: count + 3-level scan + scatter ───────────────────
__global__ __launch_bounds__(1024)
void k_prep(const float* __restrict__ seg_points) {
    __shared__ int cnt[NCELLS];
    __shared__ int cur[NCELLS];
    __shared__ int wsum[32];

    const int t    = threadIdx.x;
    const int lane = t & 31;
    const int w    = t >> 5;

    for (int i = t; i < NCELLS; i += 1024) cnt[i] = 0;
    __syncthreads();

    float xk[4], yk[4];
    int   ck[4];
    #pragma unroll
    for (int k = 0; k < 4; k++) {
        const int i = t + k * 1024;
        float x = seg_points[i * 3 + 0];
        float y = seg_points[i * 3 + 1];
        xk[k] = x; yk[k] = y;
        ck[k] = cell_of(x, y);
        atomicAdd(&cnt[ck[k]], 1);
    }
    __syncthreads();

    // 3-level exclusive scan: 3 cells per thread
    const int base = t * 3;
    int v0 = (base + 0 < NCELLS) ? cnt[base + 0] : 0;
    int v1 = (base + 1 < NCELLS) ? cnt[base + 1] : 0;
    int v2 = (base + 2 < NCELLS) ? cnt[base + 2] : 0;
    int s  = v0 + v1 + v2;

    int incl = s;
    #pragma unroll
    for (int d = 1; d < 32; d <<= 1) {
        int up = __shfl_up_sync(0xffffffffu, incl, d);
        if (lane >= d) incl += up;
    }
    if (lane == 31) wsum[w] = incl;
    __syncthreads();
    if (w == 0) {
        int ws = wsum[lane];
        int wi = ws;
        #pragma unroll
        for (int d = 1; d < 32; d <<= 1) {
            int up = __shfl_up_sync(0xffffffffu, wi, d);
            if (lane >= d) wi += up;
        }
        wsum[lane] = wi - ws;
    }
    __syncthreads();

    const int excl = incl - s + wsum[w];
    if (base + 0 < NCELLS) { g_bin_start[base + 0] = excl;           cur[base + 0] = excl; }
    if (base + 1 < NCELLS) { g_bin_start[base + 1] = excl + v0;      cur[base + 1] = excl + v0; }
    if (base + 2 < NCELLS) { g_bin_start[base + 2] = excl + v0 + v1; cur[base + 2] = excl + v0 + v1; }
    if (t == 0) g_bin_start[NCELLS] = N_POINTS;
    __syncthreads();

    #pragma unroll
    for (int k = 0; k < 4; k++) {
        const int pos = atomicAdd(&cur[ck[k]], 1);
        g_sorted[pos] = make_float4(xk[k], yk[k], __int_as_float(t + k * 1024), 0.0f);
    }
}

// ── Query (16 lanes per pillar) + fuse (warp per 2 pillars) ─────────────
// 256 threads/block → 16 pillars/block → grid 1024
__global__ __launch_bounds__(256)
void k_query_fuse(const float* __restrict__ pillar_feature,
                  const int*   __restrict__ coors,
                  const float* __restrict__ seg_feats,
                  float*       __restrict__ out) {
    __shared__ int4 sidx[16];

    const int t    = threadIdx.x;
    const int warp = t >> 5;
    const int lane = t & 31;
    const int sub  = lane & 15;           // lane within group of 16
    const int pl   = t >> 4;              // pillar within block (0..15)
    const int m    = blockIdx.x * 16 + pl;

    // ── Phase A: 16-lane ball query ──
    {
        const float px = ((float)__ldg(&coors[m * 4 + 3]) + 0.5f) * VX;
        const float py = ((float)__ldg(&coors[m * 4 + 2]) + 0.5f) * VY + PCY;

        const int cx = min(max((int)floorf(px), 0), GW - 1);
        const int cy = min(max((int)floorf(py + 25.6f), 0), GW - 1);
        const int cx0 = max(cx - 1, 0), cx1 = min(cx + 1, GW - 1);
        const int cy0 = max(cy - 1, 0), cy1 = min(cy + 1, GW - 1);
        const int cyn = cy1 - cy0;        // 1 or 2 extra rows

        // Hoist all row ranges: 6 independent loads (MLP)
        int s0, e0, s1, e1, s2, e2;
        s0 = __ldg(&g_bin_start[cy0 * GW + cx0]);
        e0 = __ldg(&g_bin_start[cy0 * GW + cx1 + 1]);
        {
            const int gy1 = min(cy0 + 1, cy1);
            s1 = __ldg(&g_bin_start[gy1 * GW + cx0]);
            e1 = __ldg(&g_bin_start[gy1 * GW + cx1 + 1]);
            const int gy2 = cy1;
            s2 = __ldg(&g_bin_start[gy2 * GW + cx0]);
            e2 = __ldg(&g_bin_start[gy2 * GW + cx1 + 1]);
        }
        if (cyn < 1) { s1 = 0; e1 = 0; }
        if (cyn < 2) { s2 = 0; e2 = 0; }

        // per-lane 4 smallest in-radius indices (sorted ascending)
        unsigned c0 = SENT, c1 = SENT, c2 = SENT, c3 = SENT;

        #define SCAN_ROW(S, E)                                               \
            for (int j = (S) + sub; j < (E); j += 16) {                      \
                float4 p = g_sorted[j];                                      \
                float dx = px - p.x;                                         \
                float dy = py - p.y;                                         \
                if (dx * dx + dy * dy < RADIUS2) {                           \
                    unsigned v = (unsigned)__float_as_int(p.z);              \
                    if (v < c3) {                                            \
                        c3 = v;                                              \
                        unsigned tmp;                                        \
                        if (c3 < c2) { tmp = c2; c2 = c3; c3 = tmp; }        \
                        if (c2 < c1) { tmp = c1; c1 = c2; c2 = tmp; }        \
                        if (c1 < c0) { tmp = c0; c0 = c1; c1 = tmp; }        \
                    }                                                        \
                }                                                            \
            }
        SCAN_ROW(s0, e0)
        SCAN_ROW(s1, e1)
        SCAN_ROW(s2, e2)
        #undef SCAN_ROW

        // 16-lane merge: ALWAYS 4 rounds, no divergent exit around shuffles.
        unsigned res0, res1, res2, res3;
        {
            unsigned a, mn;
            #define QMIN(dst)                                                \
                a  = min(c0, __shfl_xor_sync(0xffffffffu, c0, 1, 16));       \
                a  = min(a,  __shfl_xor_sync(0xffffffffu, a,  2, 16));       \
                a  = min(a,  __shfl_xor_sync(0xffffffffu, a,  4, 16));       \
                mn = min(a,  __shfl_xor_sync(0xffffffffu, a,  8, 16));       \
                dst = mn;                                                    \
                if (c0 == mn && mn != SENT) { c0 = c1; c1 = c2; c2 = c3; c3 = SENT; }
            QMIN(res0)
            QMIN(res1)
            QMIN(res2)
            QMIN(res3)
            #undef QMIN
        }

        int i0, i1, i2, i3;
        if (res0 == SENT) { i0 = i1 = i2 = i3 = 0; }
        else {
            i0 = (int)res0;
            i1 = (res1 == SENT) ? i0 : (int)res1;
            i2 = (res2 == SENT) ? i0 : (int)res2;
            i3 = (res3 == SENT) ? i0 : (int)res3;
        }
        if (sub == 0) sidx[pl] = make_int4(i0, i1, i2, i3);
    }
    __syncthreads();

    // ── Phase B: warp-per-pillar coalesced fuse (2 pillars per warp) ──
    const int pbase = blockIdx.x * 16 + warp * 2;

    #pragma unroll
    for (int k = 0; k < 2; k++) {
        const int p = pbase + k;
        const int4 id = sidx[warp * 2 + k];

        const size_t mrow = (size_t)p * C_FEAT;
        float v0 = pillar_feature[mrow + lane];
        float v1 = pillar_feature[mrow + lane + 32];

        // Reference quirk: flag = (sum of indices) > 0
        if (id.x + id.y + id.z + id.w > 0) {
            const size_t r0 = (size_t)id.x * C_FEAT;
            const size_t r1 = (size_t)id.y * C_FEAT;
            const size_t r2 = (size_t)id.z * C_FEAT;
            const size_t r3 = (size_t)id.w * C_FEAT;

            float a0 = seg_feats[r0 + lane];
            float a1 = seg_feats[r1 + lane];
            float a2 = seg_feats[r2 + lane];
            float a3 = seg_feats[r3 + lane];
            float b0 = seg_feats[r0 + lane + 32];
            float b1 = seg_feats[r1 + lane + 32];
            float b2 = seg_feats[r2 + lane + 32];
            float b3 = seg_feats[r3 + lane + 32];

            v0 += fmaxf(fmaxf(a0, a1), fmaxf(a2, a3));
            v1 += fmaxf(fmaxf(b0, b1), fmaxf(b2, b3));
        }

        out[mrow + lane]      = v0;
        out[mrow + lane + 32] = v1;
    }
}

extern "C" void kernel_launch(void* const* d_in, const int* in_sizes, int n_in,
                              void* d_out, int out_size) {
    const float* pillar_feature = (const float*)d_in[0];  // [M, 64]
    const int*   coors          = (const int*)  d_in[1];  // [M, 4]
    const float* seg_feats      = (const float*)d_in[2];  // [N, 64]
    const float* seg_points     = (const float*)d_in[3];  // [N, 3]
    float* out = (float*)d_out;                            // [M, 64]

    k_prep<<<1, 1024>>>(seg_points);
    k_query_fuse<<<M_PILLARS / 16, 256>>>(pillar_feature, coors, seg_feats, out);
}